// round 4
// baseline (speedup 1.0000x reference)
#include <cuda_runtime.h>

// Inv1x1ConvPermute: kernel matrix is a permutation matrix -> pure channel permute.
// out[b,t,o] = x[b,t, g_src[o]], g_src[o] = row index of the 1 in column o.
//
// Single fused kernel, R2's warp-autonomous gather preserved exactly:
//  - blocks 0..63 extract the inverse permutation (1 float4/thread over kmat),
//    publish via threadfence + counter (idempotent across graph replays).
//  - every warp: issue 4 streaming float4 loads + coalesced STS FIRST (no perm
//    needed), then per-warp poll of the counter (overlaps the wave-1 wait with
//    the DRAM loads), then scattered LDS gather + coalesced streaming stores.
//  - no block-wide barrier in phase 2; warps stay decoupled.

#define C 256
#define NBUILD 64
#define WARPS_PER_BLOCK 8
#define ROWS_PER_WARP 2
#define ROWS_PER_BLOCK (WARPS_PER_BLOCK * ROWS_PER_WARP)   // 16

__device__ int g_src[C];   // g_src[o] = input channel feeding output channel o
__device__ int g_done;     // monotone build counter (accumulates across replays)

__global__ __launch_bounds__(256) void permute_fused_kernel(const float* __restrict__ x,
                                                            const float* __restrict__ kmat,
                                                            float* __restrict__ out) {
    __shared__ float s[ROWS_PER_BLOCK][C];

    int tid  = threadIdx.x;
    int bid  = blockIdx.x;
    int w    = tid >> 5;
    int lane = tid & 31;

    // ---- Phase 1: blocks 0..63 build the inverse permutation ----
    if (bid < NBUILD) {
        int e = bid * 256 + tid;            // float4 index over kmat (64*256*4 = 256*256)
        int i = e >> 6;                     // kmat row (input channel)
        int c = (e & 63) * 4;               // first column of this thread's float4
        float4 v = reinterpret_cast<const float4*>(kmat)[e];
        if (v.x != 0.0f) g_src[c + 0] = i;
        if (v.y != 0.0f) g_src[c + 1] = i;
        if (v.z != 0.0f) g_src[c + 2] = i;
        if (v.w != 0.0f) g_src[c + 3] = i;
        __threadfence();                    // publish g_src writes
        __syncthreads();
        if (tid == 0) atomicAdd(&g_done, 1);
    }

    // ---- Phase 2: warp-autonomous permute of 2 rows/warp ----
    long long row0 = ((long long)bid * WARPS_PER_BLOCK + w) * ROWS_PER_WARP;

    // Issue the x loads and smem fill BEFORE waiting on the perm (overlap).
    const float4* xin = reinterpret_cast<const float4*>(x + row0 * C);
    float4 v00 = __ldcs(&xin[lane]);
    float4 v01 = __ldcs(&xin[lane + 32]);
    float4 v10 = __ldcs(&xin[lane + 64]);
    float4 v11 = __ldcs(&xin[lane + 96]);

    float* r0 = s[w * ROWS_PER_WARP + 0];
    float* r1 = s[w * ROWS_PER_WARP + 1];
    *reinterpret_cast<float4*>(&r0[lane * 4])        = v00;
    *reinterpret_cast<float4*>(&r0[(lane + 32) * 4]) = v01;
    *reinterpret_cast<float4*>(&r1[lane * 4])        = v10;
    *reinterpret_cast<float4*>(&r1[(lane + 32) * 4]) = v11;

    // Per-warp wait for the permutation (wave-1 only; later waves pass through).
    if (lane == 0) {
        while (*(volatile int*)&g_done < NBUILD) __nanosleep(128);
    }
    __syncwarp();          // releases lanes AND orders STS -> LDS
    __threadfence();       // acquire side for g_src

    // Source indices, read via L2 (coherent with the builders' stores).
    int4 src0 = __ldcg(&reinterpret_cast<const int4*>(g_src)[lane]);
    int4 src1 = __ldcg(&reinterpret_cast<const int4*>(g_src)[lane + 32]);

    // Gather through shared + coalesced streaming stores.
    float4* oout = reinterpret_cast<float4*>(out + row0 * C);
    float4 o00, o01, o10, o11;
    o00.x = r0[src0.x]; o00.y = r0[src0.y]; o00.z = r0[src0.z]; o00.w = r0[src0.w];
    o01.x = r0[src1.x]; o01.y = r0[src1.y]; o01.z = r0[src1.z]; o01.w = r0[src1.w];
    o10.x = r1[src0.x]; o10.y = r1[src0.y]; o10.z = r1[src0.z]; o10.w = r1[src0.w];
    o11.x = r1[src1.x]; o11.y = r1[src1.y]; o11.z = r1[src1.z]; o11.w = r1[src1.w];
    __stcs(&oout[lane],      o00);
    __stcs(&oout[lane + 32], o01);
    __stcs(&oout[lane + 64], o10);
    __stcs(&oout[lane + 96], o11);
}

extern "C" void kernel_launch(void* const* d_in, const int* in_sizes, int n_in,
                              void* d_out, int out_size) {
    const float* x    = (const float*)d_in[0];   // [16,16384,256]
    const float* kmat = (const float*)d_in[1];   // [256,256] permutation matrix
    float* out        = (float*)d_out;

    long long total = (long long)in_sizes[0];    // B*T*C
    int nrows = (int)(total / C);                // 262144
    int grid  = nrows / ROWS_PER_BLOCK;          // 16384

    permute_fused_kernel<<<grid, 256>>>(x, kmat, out);
}

// round 5
// speedup vs baseline: 1.4167x; 1.4167x over previous
#include <cuda_runtime.h>

// Inv1x1ConvPermute: kernel matrix is a permutation matrix (shuffled identity).
// out[b,t,o] = x[b,t, src[o]] -- a pure channel gather. DRAM-bound: 512 MiB traffic.
//
// Two kernels (fusion tested twice, loses to per-warp acquire cost):
//  1) slim perm extraction: 64 blocks x 256 threads, one float4/thread (~2us)
//  2) R2's warp-autonomous gather: 2 rows/warp, MLP=4, no block barrier (78.5us)

#define C 256
#define WARPS_PER_BLOCK 8
#define ROWS_PER_WARP 2
#define ROWS_PER_BLOCK (WARPS_PER_BLOCK * ROWS_PER_WARP)   // 16

__device__ int g_src[C];  // g_src[o] = input channel feeding output channel o

__global__ __launch_bounds__(256) void build_perm_kernel(const float* __restrict__ kmat) {
    int e = blockIdx.x * 256 + threadIdx.x;  // float4 index over kmat (64*256 = 16384)
    int i = e >> 6;                          // kmat row (input channel)
    int c = (e & 63) * 4;                    // first column of this float4
    float4 v = reinterpret_cast<const float4*>(kmat)[e];
    if (v.x != 0.0f) g_src[c + 0] = i;
    if (v.y != 0.0f) g_src[c + 1] = i;
    if (v.z != 0.0f) g_src[c + 2] = i;
    if (v.w != 0.0f) g_src[c + 3] = i;
}

__global__ __launch_bounds__(256) void gather_kernel(const float* __restrict__ x,
                                                     float* __restrict__ out) {
    __shared__ float s[ROWS_PER_BLOCK][C];

    int tid  = threadIdx.x;
    int w    = tid >> 5;     // warp 0..7
    int lane = tid & 31;

    long long row0 = ((long long)blockIdx.x * WARPS_PER_BLOCK + w) * ROWS_PER_WARP;

    // Per-lane source indices for float4 slots (lane) and (lane+32), held in regs.
    int4 src0 = reinterpret_cast<const int4*>(g_src)[lane];
    int4 src1 = reinterpret_cast<const int4*>(g_src)[lane + 32];

    // Front-batched loads: 4 independent float4 (MLP=4), streaming (no reuse).
    const float4* xin = reinterpret_cast<const float4*>(x + row0 * C);
    float4 v00 = __ldcs(&xin[lane]);         // row 0, first half
    float4 v01 = __ldcs(&xin[lane + 32]);    // row 0, second half
    float4 v10 = __ldcs(&xin[lane + 64]);    // row 1, first half
    float4 v11 = __ldcs(&xin[lane + 96]);    // row 1, second half

    float* r0 = s[w * ROWS_PER_WARP + 0];
    float* r1 = s[w * ROWS_PER_WARP + 1];
    *reinterpret_cast<float4*>(&r0[lane * 4])        = v00;
    *reinterpret_cast<float4*>(&r0[(lane + 32) * 4]) = v01;
    *reinterpret_cast<float4*>(&r1[lane * 4])        = v10;
    *reinterpret_cast<float4*>(&r1[(lane + 32) * 4]) = v11;
    __syncwarp();

    // Gather through shared, coalesced float4 streaming stores.
    float4* oout = reinterpret_cast<float4*>(out + row0 * C);
    float4 o00, o01, o10, o11;
    o00.x = r0[src0.x]; o00.y = r0[src0.y]; o00.z = r0[src0.z]; o00.w = r0[src0.w];
    o01.x = r0[src1.x]; o01.y = r0[src1.y]; o01.z = r0[src1.z]; o01.w = r0[src1.w];
    o10.x = r1[src0.x]; o10.y = r1[src0.y]; o10.z = r1[src0.z]; o10.w = r1[src0.w];
    o11.x = r1[src1.x]; o11.y = r1[src1.y]; o11.z = r1[src1.z]; o11.w = r1[src1.w];
    __stcs(&oout[lane],      o00);
    __stcs(&oout[lane + 32], o01);
    __stcs(&oout[lane + 64], o10);
    __stcs(&oout[lane + 96], o11);
}

extern "C" void kernel_launch(void* const* d_in, const int* in_sizes, int n_in,
                              void* d_out, int out_size) {
    const float* x    = (const float*)d_in[0];   // [16,16384,256]
    const float* kmat = (const float*)d_in[1];   // [256,256] permutation matrix
    float* out        = (float*)d_out;

    long long total = (long long)in_sizes[0];    // B*T*C elements
    int nrows = (int)(total / C);                // 262144

    build_perm_kernel<<<64, 256>>>(kmat);

    int grid = nrows / ROWS_PER_BLOCK;           // 16384 blocks
    gather_kernel<<<grid, 256>>>(x, out);
}